// round 16
// baseline (speedup 1.0000x reference)
#include <cuda_runtime.h>
#include <cstdint>
#include <cstddef>

#define DI __device__ __forceinline__

namespace {
constexpr int IN_DIM  = 1024;
constexpr int MEM_DIM = 512;
constexpr int N_NODES = 100000;
constexpr int BATCH   = 65536;

constexpr int BM = 128, BN = 256, BK = 32;
constexpr int MT = BATCH / BM;     // 512
constexpr int NT = MEM_DIM / BN;   // 2
constexpr int KC = IN_DIM / BK;    // 32
constexpr int THREADS = 288;       // 8 consumer warps (2x4, warp 64x64) + 1 producer warp
constexpr int STAGES = 4;

// smem: control block [0,1024) holds mbarriers; then 4 stages of 48KB.
// Stage: A[128 rows][128B] + B[256 rows][128B]; a row = 32 fp32 (one BK chunk),
// 16B units XOR-swizzled by (row&7) for conflict-free ldmatrix.
constexpr int CTRL        = 1024;
constexpr int SA_BYTES    = BM * 128;               // 16 KB
constexpr int SB_BYTES    = BN * 128;               // 32 KB
constexpr int STAGE_BYTES = SA_BYTES + SB_BYTES;    // 48 KB
constexpr int SMEM_BYTES  = CTRL + STAGES * STAGE_BYTES;   // 197632
}  // namespace

// ---------------- base-ISA helpers (NO tcgen05 — target is plain sm_103) ----------------

DI uint32_t smem_u32(const void* p) {
    uint32_t a;
    asm("{ .reg .u64 t; cvta.to.shared.u64 t, %1; cvt.u32.u64 %0, t; }" : "=r"(a) : "l"(p));
    return a;
}

DI uint32_t f2tf32(uint32_t fbits) {   // round-to-nearest tf32 on raw fp32 bits
    uint32_t r;
    asm("cvt.rna.tf32.f32 %0, %1;" : "=r"(r) : "r"(fbits));
    return r;
}

DI void ldsm_x4(uint32_t* r, uint32_t addr) {
    asm volatile("ldmatrix.sync.aligned.m8n8.x4.shared.b16 {%0,%1,%2,%3}, [%4];"
                 : "=r"(r[0]), "=r"(r[1]), "=r"(r[2]), "=r"(r[3]) : "r"(addr));
}

DI void mma_tf32(float* c, const uint32_t* a, const uint32_t* b) {
    asm volatile(
        "mma.sync.aligned.m16n8k8.row.col.f32.tf32.tf32.f32 "
        "{%0,%1,%2,%3}, {%4,%5,%6,%7}, {%8,%9}, {%0,%1,%2,%3};"
        : "+f"(c[0]), "+f"(c[1]), "+f"(c[2]), "+f"(c[3])
        : "r"(a[0]), "r"(a[1]), "r"(a[2]), "r"(a[3]), "r"(b[0]), "r"(b[1]));
}

DI void cp_async16(uint32_t smem_addr, const void* gptr) {
    asm volatile("cp.async.cg.shared.global [%0], [%1], 16;"
                 :: "r"(smem_addr), "l"(gptr));
}

DI void cp_async_mbar_arrive(uint32_t mbar) {   // arrives when this thread's prior cp.asyncs complete
    asm volatile("cp.async.mbarrier.arrive.noinc.shared::cta.b64 [%0];"
                 :: "r"(mbar) : "memory");
}

DI void mbar_init(uint32_t mbar, uint32_t count) {
    asm volatile("mbarrier.init.shared.b64 [%0], %1;" :: "r"(mbar), "r"(count) : "memory");
}
DI void mbar_arrive(uint32_t mbar) {
    asm volatile("mbarrier.arrive.shared.b64 _, [%0];" :: "r"(mbar) : "memory");
}
DI void mbar_wait_parity(uint32_t mbar, uint32_t parity) {
    uint32_t done;
    asm volatile(
        "{\n\t.reg .pred p;\n\t"
        "mbarrier.try_wait.parity.acquire.cta.shared::cta.b64 p, [%1], %2;\n\t"
        "selp.b32 %0, 1, 0, p;\n\t}"
        : "=r"(done) : "r"(mbar), "r"(parity) : "memory");
    if (!done) {
        asm volatile(
            "{\n\t.reg .pred P1;\n\t"
            "WL_%=:\n\t"
            "mbarrier.try_wait.parity.acquire.cta.shared::cta.b64 P1, [%0], %1, 0x989680;\n\t"
            "@P1 bra.uni WD_%=;\n\t"
            "bra.uni WL_%=;\n\t"
            "WD_%=:\n\t}"
            :: "r"(mbar), "r"(parity) : "memory");
    }
}

DI void red_add_v2(float* gaddr, float x, float y) {   // vector reduction, no return (sm_90+)
    asm volatile("red.global.add.v2.f32 [%0], {%1, %2};"
                 :: "l"(gaddr), "f"(x), "f"(y) : "memory");
}

// ---------------- Kernel 1: out = concat(entity_mem, rel_mem) * (t>1 ? t/(t+1) : 1) ----------------

__global__ void init_out_kernel(const float4* __restrict__ ent, const float4* __restrict__ rel,
                                const int* __restrict__ timep, float4* __restrict__ out) {
    const long long NODE4 = (long long)N_NODES * MEM_DIM / 4;
    const long long TOT4  = NODE4 + 500LL * MEM_DIM / 4;
    long long i = (long long)blockIdx.x * blockDim.x + threadIdx.x;
    if (i >= TOT4) return;
    int t = *timep;
    float s = (t > 1) ? (float)t / (float)(t + 1) : 1.0f;
    float4 v = (i < NODE4) ? ent[i] : rel[i - NODE4];
    v.x *= s; v.y *= s; v.z *= s; v.w *= s;
    out[i] = v;
}

// ---------------- Kernel 2: warp-specialized TF32 GEMM (mbarrier ring) + vector-RED scatter ----------------

__global__ void __launch_bounds__(THREADS, 1)
gemm_scatter_kernel(const float* __restrict__ nodes_emb, const float* __restrict__ rels_emb,
                    const int* __restrict__ nodes_ids, const int* __restrict__ rels_ids,
                    const float* __restrict__ W_node, const float* __restrict__ b_node,
                    const float* __restrict__ W_rel, const float* __restrict__ b_rel,
                    const int* __restrict__ timep, float* __restrict__ out) {
    extern __shared__ char smem[];
    const uint32_t sb = smem_u32(smem);
    const int tid = threadIdx.x;
    const int lane = tid & 31;
    const int wid = tid >> 5;            // 0..7 consumers, 8 producer

    const bool is_rel = (blockIdx.x >= (unsigned)(MT * NT));
    const int bid = is_rel ? (int)blockIdx.x - MT * NT : (int)blockIdx.x;
    const int tile_n = bid & (NT - 1);
    const int tile_m = bid >> 1;

    const float* Aptr = is_rel ? rels_emb : nodes_emb;
    const float* Wptr = is_rel ? W_rel : W_node;
    const float* bias = is_rel ? b_rel : b_node;
    const int*   ids  = is_rel ? rels_ids : nodes_ids;
    float* outhalf = out + (is_rel ? (size_t)N_NODES * MEM_DIM : 0);

    const float* Abase = Aptr + (size_t)(tile_m * BM) * IN_DIM;
    const float* Wbase = Wptr + (size_t)(tile_n * BN) * IN_DIM;

    // mbarriers: full(s) = sb + s*16, empty(s) = sb + s*16 + 8
    if (tid == 0) {
#pragma unroll
        for (int s = 0; s < STAGES; ++s) {
            mbar_init(sb + s * 16, 32);      // full: 32 producer-thread async arrivals
            mbar_init(sb + s * 16 + 8, 8);   // empty: 8 consumer-warp arrivals
        }
    }
    __syncthreads();

    if (wid == 8) {
        // ================= producer warp =================
        int stage = 0, phase = 1;            // phase=1: first empty-waits pass immediately
        for (int kc = 0; kc < KC; ++kc) {
            mbar_wait_parity(sb + stage * 16 + 8, (uint32_t)phase);
            const uint32_t stg = sb + CTRL + (uint32_t)(stage * STAGE_BYTES);
            const int koff = kc * BK;
            // 3072 16B-slots: j<32 -> A (1024 slots), j>=32 -> B (2048 slots)
#pragma unroll
            for (int j = 0; j < 96; ++j) {
                const int slot = j * 32 + lane;
                const bool isA = (j < 32);
                const int s2 = isA ? slot : slot - 1024;
                const int row = s2 >> 3;
                const int k4 = s2 & 7;
                const uint32_t soff = (isA ? 0u : (uint32_t)SA_BYTES) +
                                      (uint32_t)(row * 128 + ((k4 ^ (row & 7)) << 4));
                const float* g = (isA ? Abase : Wbase) + koff + (size_t)row * IN_DIM + k4 * 4;
                cp_async16(stg + soff, g);
            }
            cp_async_mbar_arrive(sb + stage * 16);   // full(stage) when this thread's copies land
            if (++stage == STAGES) { stage = 0; phase ^= 1; }
        }
        // drain: wait for the last STAGES chunks to be consumed before exiting
#pragma unroll
        for (int s = 0; s < STAGES; ++s) {
            mbar_wait_parity(sb + stage * 16 + 8, (uint32_t)phase);
            if (++stage == STAGES) { stage = 0; phase ^= 1; }
        }
        return;
    }

    // ================= consumer warps (8: 2 x 4, warp tile 64x64) =================
    const int wm = wid & 1;
    const int wn = wid >> 1;

    const int a_khi = lane >> 4;
    uint32_t a_rowb[4]; int a_r7[4];
#pragma unroll
    for (int mt = 0; mt < 4; ++mt) {
        int row = wm * 64 + mt * 16 + (lane & 7) + ((lane >> 3) & 1) * 8;
        a_rowb[mt] = (uint32_t)(row * 128);
        a_r7[mt] = row & 7;
    }
    const int b_khi = (lane >> 3) & 1;
    uint32_t b_rowb[4]; int b_r7[4];
#pragma unroll
    for (int np = 0; np < 4; ++np) {
        int row = wn * 64 + np * 16 + (lane & 7) + ((lane >> 4) & 1) * 8;
        b_rowb[np] = (uint32_t)(SA_BYTES + row * 128);
        b_r7[np] = row & 7;
    }

    float C[4][8][4];
#pragma unroll
    for (int mt = 0; mt < 4; ++mt)
#pragma unroll
        for (int nt = 0; nt < 8; ++nt)
#pragma unroll
            for (int v = 0; v < 4; ++v) C[mt][nt][v] = 0.0f;

    int stage = 0, phase = 0;
    for (int kc = 0; kc < KC; ++kc) {
        mbar_wait_parity(sb + stage * 16, (uint32_t)phase);   // full(stage)
        const uint32_t cur = sb + CTRL + (uint32_t)(stage * STAGE_BYTES);
#pragma unroll
        for (int ks = 0; ks < 4; ++ks) {
            uint32_t afr[4][4];
#pragma unroll
            for (int mt = 0; mt < 4; ++mt) {
                uint32_t addr = cur + a_rowb[mt] + (uint32_t)(((2 * ks + a_khi) ^ a_r7[mt]) << 4);
                ldsm_x4(afr[mt], addr);
#pragma unroll
                for (int v = 0; v < 4; ++v) afr[mt][v] = f2tf32(afr[mt][v]);
            }
#pragma unroll
            for (int np = 0; np < 4; ++np) {
                uint32_t bfr[4];
                uint32_t addr = cur + b_rowb[np] + (uint32_t)(((2 * ks + b_khi) ^ b_r7[np]) << 4);
                ldsm_x4(bfr, addr);
#pragma unroll
                for (int v = 0; v < 4; ++v) bfr[v] = f2tf32(bfr[v]);
#pragma unroll
                for (int mt = 0; mt < 4; ++mt) {
                    mma_tf32(C[mt][2 * np],     afr[mt], bfr);
                    mma_tf32(C[mt][2 * np + 1], afr[mt], bfr + 2);
                }
            }
        }
        if (lane == 0) mbar_arrive(sb + stage * 16 + 8);      // empty(stage)
        if (++stage == STAGES) { stage = 0; phase ^= 1; }
    }

    // ---- epilogue: out[id[m]] += (C + bias) / (t+1), vector RED scatter (v2.f32) ----
    const int t = *timep;
    const float inv = 1.0f / (float)(t + 1);
    const int g = lane >> 2;
    const int tg = lane & 3;

    float* p[8];
#pragma unroll
    for (int mt = 0; mt < 4; ++mt) {
        int r0 = tile_m * BM + wm * 64 + mt * 16 + g;
        p[2 * mt]     = outhalf + (size_t)ids[r0] * MEM_DIM;
        p[2 * mt + 1] = outhalf + (size_t)ids[r0 + 8] * MEM_DIM;
    }
#pragma unroll
    for (int nt = 0; nt < 8; ++nt) {
        const int c = tile_n * BN + wn * 64 + nt * 8 + tg * 2;
        const float2 bv = *reinterpret_cast<const float2*>(bias + c);
#pragma unroll
        for (int mt = 0; mt < 4; ++mt) {
            red_add_v2(p[2 * mt] + c,     (C[mt][nt][0] + bv.x) * inv, (C[mt][nt][1] + bv.y) * inv);
            red_add_v2(p[2 * mt + 1] + c, (C[mt][nt][2] + bv.x) * inv, (C[mt][nt][3] + bv.y) * inv);
        }
    }
}

// ---------------- launch ----------------

extern "C" void kernel_launch(void* const* d_in, const int* in_sizes, int n_in,
                              void* d_out, int out_size) {
    const float* nodes_emb = (const float*)d_in[0];
    const float* rels_emb  = (const float*)d_in[1];
    const int*   nodes_ids = (const int*)d_in[2];
    const int*   rels_ids  = (const int*)d_in[3];
    const float* ent_mem   = (const float*)d_in[4];
    const float* rel_mem   = (const float*)d_in[5];
    const float* W_node    = (const float*)d_in[6];
    const float* b_node    = (const float*)d_in[7];
    const float* W_rel     = (const float*)d_in[8];
    const float* b_rel     = (const float*)d_in[9];
    const int*   timep     = (const int*)d_in[10];
    float* out = (float*)d_out;

    static bool attr_set = false;
    if (!attr_set) {
        cudaFuncSetAttribute(gemm_scatter_kernel,
                             cudaFuncAttributeMaxDynamicSharedMemorySize, SMEM_BYTES);
        attr_set = true;
    }

    // 1) out = scaled concat of memories
    const long long TOT4 = ((long long)N_NODES * MEM_DIM + 500LL * MEM_DIM) / 4;
    const int blocks = (int)((TOT4 + 255) / 256);
    init_out_kernel<<<blocks, 256>>>((const float4*)ent_mem, (const float4*)rel_mem, timep,
                                     (float4*)out);

    // 2) warp-specialized TF32 GEMM + scatter
    gemm_scatter_kernel<<<2 * MT * NT, THREADS, SMEM_BYTES>>>(
        nodes_emb, rels_emb, nodes_ids, rels_ids,
        W_node, b_node, W_rel, b_rel, timep, out);
}

// round 17
// speedup vs baseline: 1.2930x; 1.2930x over previous
#include <cuda_runtime.h>
#include <cstdint>
#include <cstddef>

#define DI __device__ __forceinline__

namespace {
constexpr int IN_DIM  = 1024;
constexpr int MEM_DIM = 512;
constexpr int N_NODES = 100000;
constexpr int BATCH   = 65536;

constexpr int BM = 128, BN = 256, BK = 64;
constexpr int MT = BATCH / BM;     // 512
constexpr int NT = MEM_DIM / BN;   // 2
constexpr int KC = IN_DIM / BK;    // 16
constexpr int THREADS = 256;       // 8 warps: 2 (M) x 4 (N), warp tile 64x64
constexpr int STAGES = 2;

// smem per stage: A[128 rows][256B] + B[256 rows][256B]; a row = 64 fp32 (one BK chunk),
// 16B units XOR-swizzled by (row&7) for conflict-free ldmatrix.
constexpr int SA_BYTES    = BM * 256;               // 32 KB
constexpr int SB_BYTES    = BN * 256;               // 64 KB
constexpr int STAGE_BYTES = SA_BYTES + SB_BYTES;    // 96 KB
constexpr int SMEM_BYTES  = STAGES * STAGE_BYTES;   // 192 KB
}  // namespace

// ---------------- base-ISA helpers (NO tcgen05 — target is plain sm_103) ----------------

DI uint32_t smem_u32(const void* p) {
    uint32_t a;
    asm("{ .reg .u64 t; cvta.to.shared.u64 t, %1; cvt.u32.u64 %0, t; }" : "=r"(a) : "l"(p));
    return a;
}

DI uint32_t f2tf32(uint32_t fbits) {   // round-to-nearest tf32 on raw fp32 bits
    uint32_t r;
    asm("cvt.rna.tf32.f32 %0, %1;" : "=r"(r) : "r"(fbits));
    return r;
}

DI void ldsm_x4(uint32_t* r, uint32_t addr) {
    asm volatile("ldmatrix.sync.aligned.m8n8.x4.shared.b16 {%0,%1,%2,%3}, [%4];"
                 : "=r"(r[0]), "=r"(r[1]), "=r"(r[2]), "=r"(r[3]) : "r"(addr));
}

DI void mma_tf32(float* c, const uint32_t* a, const uint32_t* b) {
    asm volatile(
        "mma.sync.aligned.m16n8k8.row.col.f32.tf32.tf32.f32 "
        "{%0,%1,%2,%3}, {%4,%5,%6,%7}, {%8,%9}, {%0,%1,%2,%3};"
        : "+f"(c[0]), "+f"(c[1]), "+f"(c[2]), "+f"(c[3])
        : "r"(a[0]), "r"(a[1]), "r"(a[2]), "r"(a[3]), "r"(b[0]), "r"(b[1]));
}

DI void cp_async16(uint32_t smem_addr, const void* gptr) {
    asm volatile("cp.async.cg.shared.global [%0], [%1], 16;"
                 :: "r"(smem_addr), "l"(gptr));
}
DI void cp_commit() { asm volatile("cp.async.commit_group;"); }
DI void cp_wait1()  { asm volatile("cp.async.wait_group 1;"); }

DI void red_add_v2(float* gaddr, float x, float y) {   // vector reduction, no return (sm_90+)
    asm volatile("red.global.add.v2.f32 [%0], {%1, %2};"
                 :: "l"(gaddr), "f"(x), "f"(y) : "memory");
}

// ---------------- Kernel 1: out = concat(entity_mem, rel_mem) * (t>1 ? t/(t+1) : 1) ----------------

__global__ void init_out_kernel(const float4* __restrict__ ent, const float4* __restrict__ rel,
                                const int* __restrict__ timep, float4* __restrict__ out) {
    // PDL: allow the dependent GEMM kernel to start launching immediately.
    // (Launch-gating only; cudaGridDependencySynchronize in the GEMM still waits
    //  for FULL completion of this grid before the scatter reads/writes `out`.)
    cudaTriggerProgrammaticLaunchCompletion();

    const long long NODE4 = (long long)N_NODES * MEM_DIM / 4;
    const long long TOT4  = NODE4 + 500LL * MEM_DIM / 4;
    long long i = (long long)blockIdx.x * blockDim.x + threadIdx.x;
    if (i >= TOT4) return;
    int t = *timep;
    float s = (t > 1) ? (float)t / (float)(t + 1) : 1.0f;
    float4 v = (i < NODE4) ? ent[i] : rel[i - NODE4];
    v.x *= s; v.y *= s; v.z *= s; v.w *= s;
    out[i] = v;
}

// ---------------- Kernel 2: TF32 mma.sync GEMM (cp.async 2-stage, BK=64) + vector-RED scatter ----------------

__global__ void __launch_bounds__(THREADS, 1)
gemm_scatter_kernel(const float* __restrict__ nodes_emb, const float* __restrict__ rels_emb,
                    const int* __restrict__ nodes_ids, const int* __restrict__ rels_ids,
                    const float* __restrict__ W_node, const float* __restrict__ b_node,
                    const float* __restrict__ W_rel, const float* __restrict__ b_rel,
                    const int* __restrict__ timep, float* __restrict__ out) {
    extern __shared__ char smem[];
    const uint32_t sb = smem_u32(smem);
    const int tid = threadIdx.x;
    const int lane = tid & 31;
    const int wid = tid >> 5;
    const int wm = wid & 1;      // warp row (2)  -> 64 M rows each
    const int wn = wid >> 1;     // warp col (4)  -> 64 N cols each

    const bool is_rel = (blockIdx.x >= (unsigned)(MT * NT));
    const int bid = is_rel ? (int)blockIdx.x - MT * NT : (int)blockIdx.x;
    const int tile_n = bid & (NT - 1);
    const int tile_m = bid >> 1;

    const float* Aptr = is_rel ? rels_emb : nodes_emb;
    const float* Wptr = is_rel ? W_rel : W_node;
    const float* bias = is_rel ? b_rel : b_node;
    const int*   ids  = is_rel ? rels_ids : nodes_ids;
    float* outhalf = out + (is_rel ? (size_t)N_NODES * MEM_DIM : 0);

    const float* Abase = Aptr + (size_t)(tile_m * BM) * IN_DIM;
    const float* Wbase = Wptr + (size_t)(tile_n * BN) * IN_DIM;

    // ---- cp.async slots: 16 16B-slots per 256B row; k4 = tid&15 is slot-invariant ----
    const int  row0 = tid >> 4;                       // 0..15
    const int  k4   = tid & 15;                       // 0..15
    const uint32_t go0 = (uint32_t)(row0 * IN_DIM + k4 * 4);
    const uint32_t st0 = (uint32_t)(row0 * 256 + ((k4 ^ (row0 & 7)) << 4));

    auto issue_chunk = [&](int kc) {   // always commits (uniform wait arithmetic)
        if (kc < KC) {
            const uint32_t go = go0 + (uint32_t)(kc * BK);
            const uint32_t stg = sb + (uint32_t)((kc & (STAGES - 1)) * STAGE_BYTES);
#pragma unroll
            for (int j = 0; j < 8; ++j)                  // A: 8 slots, stride 16 rows
                cp_async16(stg + st0 + j * 16 * 256, Abase + go + j * 16 * IN_DIM);
#pragma unroll
            for (int j = 0; j < 16; ++j)                 // B: 16 slots
                cp_async16(stg + SA_BYTES + st0 + j * 16 * 256, Wbase + go + j * 16 * IN_DIM);
        }
        cp_commit();
    };

    // ---- ldmatrix address precompute (R7 mapping, 256B row pitch) ----
    const int a_khi = lane >> 4;
    uint32_t a_rowb[4]; int a_r7[4];
#pragma unroll
    for (int mt = 0; mt < 4; ++mt) {
        int row = wm * 64 + mt * 16 + (lane & 7) + ((lane >> 3) & 1) * 8;
        a_rowb[mt] = (uint32_t)(row * 256);
        a_r7[mt] = row & 7;
    }
    const int b_khi = (lane >> 3) & 1;
    uint32_t b_rowb[4]; int b_r7[4];
#pragma unroll
    for (int np = 0; np < 4; ++np) {
        int row = wn * 64 + np * 16 + (lane & 7) + ((lane >> 4) & 1) * 8;
        b_rowb[np] = (uint32_t)(SA_BYTES + row * 256);
        b_r7[np] = row & 7;
    }

    float C[4][8][4];
#pragma unroll
    for (int mt = 0; mt < 4; ++mt)
#pragma unroll
        for (int nt = 0; nt < 8; ++nt)
#pragma unroll
            for (int v = 0; v < 4; ++v) C[mt][nt][v] = 0.0f;

    // ---- prologue: 2 chunks in flight ----
    issue_chunk(0);
    issue_chunk(1);

    // ---- main loop: 16 chunks, 8 ksteps each (R12 body, byte-identical) ----
    for (int kc = 0; kc < KC; ++kc) {
        cp_wait1();          // chunk kc complete (chunk kc+1 still outstanding)
        __syncthreads();     // data visible to all warps

        const uint32_t cur = sb + (uint32_t)((kc & (STAGES - 1)) * STAGE_BYTES);
#pragma unroll
        for (int ks = 0; ks < 8; ++ks) {
            uint32_t afr[4][4];
#pragma unroll
            for (int mt = 0; mt < 4; ++mt) {
                uint32_t addr = cur + a_rowb[mt] + (uint32_t)(((2 * ks + a_khi) ^ a_r7[mt]) << 4);
                ldsm_x4(afr[mt], addr);
#pragma unroll
                for (int v = 0; v < 4; ++v) afr[mt][v] = f2tf32(afr[mt][v]);
            }
#pragma unroll
            for (int np = 0; np < 4; ++np) {
                uint32_t bfr[4];
                uint32_t addr = cur + b_rowb[np] + (uint32_t)(((2 * ks + b_khi) ^ b_r7[np]) << 4);
                ldsm_x4(bfr, addr);
#pragma unroll
                for (int v = 0; v < 4; ++v) bfr[v] = f2tf32(bfr[v]);
#pragma unroll
                for (int mt = 0; mt < 4; ++mt) {
                    mma_tf32(C[mt][2 * np],     afr[mt], bfr);
                    mma_tf32(C[mt][2 * np + 1], afr[mt], bfr + 2);
                }
            }
        }
        __syncthreads();     // all warps done reading stage kc&1 before refilling it
        issue_chunk(kc + 2); // writes stage kc&1
    }

    // ---- PDL gate: init kernel must be fully complete before touching `out` ----
    cudaGridDependencySynchronize();

    // ---- epilogue: out[id[m]] += (C + bias) / (t+1), vector RED scatter (v2.f32) ----
    const int t = *timep;
    const float inv = 1.0f / (float)(t + 1);
    const int g = lane >> 2;
    const int tg = lane & 3;

    float* p[8];
#pragma unroll
    for (int mt = 0; mt < 4; ++mt) {
        int r0 = tile_m * BM + wm * 64 + mt * 16 + g;
        p[2 * mt]     = outhalf + (size_t)ids[r0] * MEM_DIM;
        p[2 * mt + 1] = outhalf + (size_t)ids[r0 + 8] * MEM_DIM;
    }
#pragma unroll
    for (int nt = 0; nt < 8; ++nt) {
        const int c = tile_n * BN + wn * 64 + nt * 8 + tg * 2;
        const float2 bv = *reinterpret_cast<const float2*>(bias + c);
#pragma unroll
        for (int mt = 0; mt < 4; ++mt) {
            red_add_v2(p[2 * mt] + c,     (C[mt][nt][0] + bv.x) * inv, (C[mt][nt][1] + bv.y) * inv);
            red_add_v2(p[2 * mt + 1] + c, (C[mt][nt][2] + bv.x) * inv, (C[mt][nt][3] + bv.y) * inv);
        }
    }
}

// ---------------- launch ----------------

extern "C" void kernel_launch(void* const* d_in, const int* in_sizes, int n_in,
                              void* d_out, int out_size) {
    const float* nodes_emb = (const float*)d_in[0];
    const float* rels_emb  = (const float*)d_in[1];
    const int*   nodes_ids = (const int*)d_in[2];
    const int*   rels_ids  = (const int*)d_in[3];
    const float* ent_mem   = (const float*)d_in[4];
    const float* rel_mem   = (const float*)d_in[5];
    const float* W_node    = (const float*)d_in[6];
    const float* b_node    = (const float*)d_in[7];
    const float* W_rel     = (const float*)d_in[8];
    const float* b_rel     = (const float*)d_in[9];
    const int*   timep     = (const int*)d_in[10];
    float* out = (float*)d_out;

    static bool attr_set = false;
    if (!attr_set) {
        cudaFuncSetAttribute(gemm_scatter_kernel,
                             cudaFuncAttributeMaxDynamicSharedMemorySize, SMEM_BYTES);
        attr_set = true;
    }

    // 1) out = scaled concat of memories (primary grid; triggers PDL release at entry)
    const long long TOT4 = ((long long)N_NODES * MEM_DIM + 500LL * MEM_DIM) / 4;
    const int blocks = (int)((TOT4 + 255) / 256);
    init_out_kernel<<<blocks, 256>>>((const float4*)ent_mem, (const float4*)rel_mem, timep,
                                     (float4*)out);

    // 2) GEMM + scatter, launched with Programmatic Stream Serialization so its
    //    mainloop overlaps the init kernel; the epilogue gates via griddepsync.
    cudaLaunchConfig_t cfg = {};
    cfg.gridDim = dim3((unsigned)(2 * MT * NT));
    cfg.blockDim = dim3((unsigned)THREADS);
    cfg.dynamicSmemBytes = SMEM_BYTES;
    cfg.stream = 0;
    cudaLaunchAttribute attrs[1];
    attrs[0].id = cudaLaunchAttributeProgrammaticStreamSerialization;
    attrs[0].val.programmaticStreamSerializationAllowed = 1;
    cfg.attrs = attrs;
    cfg.numAttrs = 1;
    cudaLaunchKernelEx(&cfg, gemm_scatter_kernel,
                       nodes_emb, rels_emb, nodes_ids, rels_ids,
                       W_node, b_node, W_rel, b_rel, timep, out);
}